// round 14
// baseline (speedup 1.0000x reference)
#include <cuda_runtime.h>

#define T_STEPS 4096
#define BATCH 64
#define IN_DIM 4
#define HID 256
#define OUT_DIM 2
#define HALF 128
#define HPAD 132            // 128 floats + 4-float pad (keeps 16B alignment)
#define NBUF 4              // read t&3, write (t+1)&3, wipe (t+2)&3
#define HXB  (NBUF * 2 * HPAD * 4)   // byte size of one batch's buffer set (4224)

// hidden-state history for the output head: [T, B, H] fp32 = 268 MB scratch
__device__ float g_hs[(size_t)T_STEPS * BATCH * HID];

__device__ __forceinline__ void fma2(unsigned long long &acc,
                                     unsigned long long a,
                                     unsigned long long b) {
    asm("fma.rn.f32x2 %0, %1, %2, %0;" : "+l"(acc) : "l"(a), "l"(b));
}

__device__ __forceinline__ float2 unpack2(unsigned long long v) {
    float2 f;
    asm("mov.b64 {%0, %1}, %2;" : "=f"(f.x), "=f"(f.y) : "l"(v));
    return f;
}

__device__ __forceinline__ unsigned int smem_u32(const void* p) {
    unsigned int a;
    asm("{ .reg .u64 t; cvta.to.shared.u64 t, %1; cvt.u32.u64 %0, t; }"
        : "=r"(a) : "l"(p));
    return a;
}

__device__ __forceinline__ unsigned int mapa_rank(unsigned int laddr,
                                                  unsigned int target) {
    unsigned int r;
    asm("mapa.shared::cluster.u32 %0, %1, %2;" : "=r"(r) : "r"(laddr), "r"(target));
    return r;
}

// 128-MAC dot with NaN-retry (R10's proven verifier). Volatile 16B LDS so
// each retry re-reads SMEM. Non-NaN result proves all 128 inputs are real.
__device__ __forceinline__ float dot128_retry(const unsigned long long* __restrict__ wh,
                                              unsigned int a) {
    float part;
    unsigned int bad;
    do {
        unsigned long long c0 = 0ull, c1 = 0ull, c2 = 0ull, c3 = 0ull;
#pragma unroll
        for (int m = 0; m < 32; m += 2) {
            unsigned long long x0, x1, x2, x3;
            asm volatile("ld.volatile.shared.v2.u64 {%0, %1}, [%2];"
                         : "=l"(x0), "=l"(x1) : "r"(a + m * 16));
            asm volatile("ld.volatile.shared.v2.u64 {%0, %1}, [%2];"
                         : "=l"(x2), "=l"(x3) : "r"(a + m * 16 + 16));
            fma2(c0, wh[2 * m],     x0);
            fma2(c1, wh[2 * m + 1], x1);
            fma2(c2, wh[2 * m + 2], x2);
            fma2(c3, wh[2 * m + 3], x3);
        }
        float2 f0 = unpack2(c0), f1 = unpack2(c1);
        float2 f2 = unpack2(c2), f3 = unpack2(c3);
        part = ((f0.x + f0.y) + (f1.x + f1.y)) + ((f2.x + f2.y) + (f3.x + f3.y));
        unsigned int v = __float_as_uint(part);          // fast-math-immune
        bad = ((v & 0x7fffffffu) > 0x7f800000u) ? 1u : 0u;
    } while (__any_sync(0xffffffffu, bad));
    return part;
}

// ---------------------------------------------------------------------------
// Recurrence: output-split, 2-CTA cluster, TWO batches per cluster on the
// R10 barrier-free NaN-sentinel fabric. T_vis (DSMEM visibility, the proven
// ~900cy residual) is AMORTIZED over 2 steps: while batch A's pushes are in
// flight, we compute batch B. Steady state: period = max(2C, C+T_vis) per
// 2 steps instead of (C+T_vis) per step.
// Weights are SHARED between batches (same output row jg) -> the 128 weight
// registers do not double. Batch-B SMEM addresses = batch-A address + 4224
// (immediate), so no extra address registers.
// Publish is uniform via st.shared::cluster: p==rank lanes target their own
// CTA (mapa to self), p!=rank lanes target the peer.
// ---------------------------------------------------------------------------
__global__ void __launch_bounds__(256, 1) __cluster_dims__(2, 1, 1)
elman_recurrence(const float* __restrict__ input,
                 const float* __restrict__ Wi,
                 const float* __restrict__ bi,
                 const float* __restrict__ Wh,
                 const float* __restrict__ bh) {
    // hx[batch][buf][khalf][slot]; khalf==rank written locally (via self-
    // mapa st.shared::cluster), 1-rank by peer pushes.
    __shared__ __align__(16) float hx[2][NBUF][2][HPAD];

    const int tid  = threadIdx.x;
    const int rank = blockIdx.x & 1;
    const int c    = blockIdx.x >> 1;
    const int bA   = 2 * c;
    const unsigned int peer = rank ^ 1;
    const int jl = tid >> 1;                // output index 0..127
    const int p  = tid & 1;                 // k-half this lane accumulates
    const int jg = HALF * rank + jl;        // global output index

    // --- loop-invariant weights Wh[jg][128p .. +128) in registers ---
    unsigned long long wh[64];
    {
        const ulonglong2* wsrc =
            (const ulonglong2*)(Wh + (size_t)jg * HID + p * HALF);
#pragma unroll
        for (int m = 0; m < 32; ++m) {
            ulonglong2 v = __ldg(wsrc + m);
            wh[2 * m]     = v.x;
            wh[2 * m + 1] = v.y;
        }
    }

    const float4 wi4 = __ldg((const float4*)(Wi + (size_t)jg * IN_DIM));
    const float  cb  = __ldg(bi + jg) + __ldg(bh + jg);

    // --- per-buffer addresses (batch A; batch B = +HXB immediate) ---
    unsigned int rd_a[NBUF];    // read base:   &hx[0][s][p][0]
    unsigned int wsl_a[NBUF];   // my read slot: &hx[0][s][p][jl] (wipe target)
    unsigned int pub_a[NBUF];   // publish slot: (self or peer) &hx[0][s][rank][jl]
#pragma unroll
    for (int s = 0; s < NBUF; ++s) {
        rd_a[s]  = smem_u32(&hx[0][s][p][0]);
        wsl_a[s] = smem_u32(&hx[0][s][p][jl]);
        pub_a[s] = mapa_rank(smem_u32(&hx[0][s][rank][jl]),
                             (p == rank) ? (unsigned)rank : peer);
    }

    // --- init: buf0 = h0 = 0; bufs 1..3 = NaN; both batches ---
    if (tid < HPAD) {
#pragma unroll
        for (int bb = 0; bb < 2; ++bb) {
            hx[bb][0][0][tid] = 0.f;
            hx[bb][0][1][tid] = 0.f;
#pragma unroll
            for (int s = 1; s < NBUF; ++s) {
                ((unsigned int*)&hx[bb][s][0][0])[tid] = 0x7fffffffu;
                ((unsigned int*)&hx[bb][s][1][0])[tid] = 0x7fffffffu;
            }
        }
    }
    __syncthreads();
    // one-time: peer must observe our init before its first pushes land here
    asm volatile("barrier.cluster.arrive.aligned;" ::: "memory");
    asm volatile("barrier.cluster.wait.aligned;" ::: "memory");

    float4 xinA = __ldg((const float4*)(input + (size_t)bA * IN_DIM));
    float4 xinB = __ldg((const float4*)(input + (size_t)(bA + 1) * IN_DIM));
    float* hsb = g_hs + (size_t)bA * HID + (size_t)jg;   // batch B = +HID

    for (int t = 0; t < T_STEPS; ++t) {
        const int cur = t & 3;
        const int nxt = (t + 1) & 3;
        const int wb  = (t + 2) & 3;

        // 1. wipe my read slots (both batches) in the buffer due for reuse
        asm volatile("st.volatile.shared.u32 [%0], %1;"
                     :: "r"(wsl_a[wb]), "r"(0x7fffffffu) : "memory");
        asm volatile("st.volatile.shared.u32 [%0+4224], %1;"
                     :: "r"(wsl_a[wb]), "r"(0x7fffffffu) : "memory");

        // prefetch next xi for both batches (independent; adjacent rows)
        float4 xnA = xinA, xnB = xinB;
        if (t + 1 < T_STEPS) {
            const float4* nx = (const float4*)(input +
                               ((size_t)(t + 1) * BATCH + bA) * IN_DIM);
            xnA = __ldg(nx);
            xnB = __ldg(nx + 1);
        }

        // ---- batch A: retry dot (absorbs the wait), tanh, publish ----
        float partA = dot128_retry(wh, rd_a[cur]);
        partA += __shfl_xor_sync(0xffffffffu, partA, 1);
        float hnA = tanhf(partA + xinA.x * wi4.x + xinA.y * wi4.y +
                          xinA.z * wi4.z + xinA.w * wi4.w + cb);
        asm volatile("st.shared::cluster.f32 [%0], %1;"
                     :: "r"(pub_a[nxt]), "f"(hnA) : "memory");
        if (p == 1) hsb[(size_t)t * (BATCH * HID)] = hnA;

        // ---- batch B: its data arrived while A was processed ----
        float partB = dot128_retry(wh, rd_a[cur] + HXB);
        partB += __shfl_xor_sync(0xffffffffu, partB, 1);
        float hnB = tanhf(partB + xinB.x * wi4.x + xinB.y * wi4.y +
                          xinB.z * wi4.z + xinB.w * wi4.w + cb);
        asm volatile("st.shared::cluster.f32 [%0+4224], %1;"
                     :: "r"(pub_a[nxt]), "f"(hnB) : "memory");
        if (p == 1) hsb[(size_t)t * (BATCH * HID) + HID] = hnB;

        xinA = xnA;
        xinB = xnB;
        // NO __syncthreads in the loop (sentinels carry all ordering)
    }

    // keep SMEM alive until the peer's last in-flight pushes are irrelevant
    asm volatile("barrier.cluster.arrive.aligned;" ::: "memory");
    asm volatile("barrier.cluster.wait.aligned;" ::: "memory");
}

// ---------------------------------------------------------------------------
// Output head: out[t,b,:] = tanh(hs[t,b,:] @ Wf^T + bf). One warp per row,
// grid-stride; memory-bound (streams 268 MB of hs at ~69% of HBM peak).
// ---------------------------------------------------------------------------
__global__ void __launch_bounds__(256)
elman_head(const float* __restrict__ Wf,
           const float* __restrict__ bf,
           float* __restrict__ out) {
    const int lane   = threadIdx.x & 31;
    const int gwarp  = (blockIdx.x * blockDim.x + threadIdx.x) >> 5;
    const int nwarps = (gridDim.x * blockDim.x) >> 5;

    const float bf0 = __ldg(bf + 0);
    const float bf1 = __ldg(bf + 1);

    const float4* wf0p = (const float4*)(Wf) + lane * 2;
    const float4* wf1p = (const float4*)(Wf + HID) + lane * 2;
    const float4 w00 = __ldg(wf0p), w01 = __ldg(wf0p + 1);
    const float4 w10 = __ldg(wf1p), w11 = __ldg(wf1p + 1);

    const int nrows = T_STEPS * BATCH;
    for (int row = gwarp; row < nrows; row += nwarps) {
        const float4* h = (const float4*)(g_hs + (size_t)row * HID) + lane * 2;
        float4 h0 = h[0], h1 = h[1];
        float s0 = h0.x * w00.x + h0.y * w00.y + h0.z * w00.z + h0.w * w00.w +
                   h1.x * w01.x + h1.y * w01.y + h1.z * w01.z + h1.w * w01.w;
        float s1 = h0.x * w10.x + h0.y * w10.y + h0.z * w10.z + h0.w * w10.w +
                   h1.x * w11.x + h1.y * w11.y + h1.z * w11.z + h1.w * w11.w;
#pragma unroll
        for (int o = 16; o; o >>= 1) {
            s0 += __shfl_xor_sync(0xffffffffu, s0, o);
            s1 += __shfl_xor_sync(0xffffffffu, s1, o);
        }
        if (lane == 0) {
            out[(size_t)row * OUT_DIM + 0] = tanhf(s0 + bf0);
            out[(size_t)row * OUT_DIM + 1] = tanhf(s1 + bf1);
        }
    }
}

// nop as the 3rd launch: the harness prepends 2 launches, so ncu's capture
// (skip 5, take #6) lands on OUR 4th launch = the 2nd call's RECURRENCE.
__global__ void elman_nop() {}

extern "C" void kernel_launch(void* const* d_in, const int* in_sizes, int n_in,
                              void* d_out, int out_size) {
    // metadata order: input, target, Wi, bi, Wh, bh, Wf, bf
    const float* input = (const float*)d_in[0];
    const float* Wi = (const float*)d_in[2];
    const float* bi = (const float*)d_in[3];
    const float* Wh = (const float*)d_in[4];
    const float* bh = (const float*)d_in[5];
    const float* Wf = (const float*)d_in[6];
    const float* bf = (const float*)d_in[7];
    float* out = (float*)d_out;

    // 32 clusters x 2 CTAs, 2 batches per cluster
    elman_recurrence<<<BATCH, 256>>>(input, Wi, bi, Wh, bh);
    elman_head<<<2048, 256>>>(Wf, bf, out);
    elman_nop<<<1, 32>>>();
}

// round 15
// speedup vs baseline: 1.3524x; 1.3524x over previous
#include <cuda_runtime.h>

#define T_STEPS 4096
#define BATCH 64
#define IN_DIM 4
#define HID 256
#define OUT_DIM 2
#define HALF 128
#define HPAD 132            // 128 floats + 4-float pad between buffers
#define NBUF 4              // read t&3, write (t+1)&3, wipe (t+2)&3

// hidden-state history for the output head: [T, B, H] fp32 = 268 MB scratch
__device__ float g_hs[(size_t)T_STEPS * BATCH * HID];

__device__ __forceinline__ void fma2(unsigned long long &acc,
                                     unsigned long long a,
                                     unsigned long long b) {
    asm("fma.rn.f32x2 %0, %1, %2, %0;" : "+l"(acc) : "l"(a), "l"(b));
}

__device__ __forceinline__ float2 unpack2(unsigned long long v) {
    float2 f;
    asm("mov.b64 {%0, %1}, %2;" : "=f"(f.x), "=f"(f.y) : "l"(v));
    return f;
}

__device__ __forceinline__ unsigned int smem_u32(const void* p) {
    unsigned int a;
    asm("{ .reg .u64 t; cvta.to.shared.u64 t, %1; cvt.u32.u64 %0, t; }"
        : "=r"(a) : "l"(p));
    return a;
}

__device__ __forceinline__ unsigned int mapa_peer(unsigned int laddr,
                                                  unsigned int peer) {
    unsigned int r;
    asm("mapa.shared::cluster.u32 %0, %1, %2;" : "=r"(r) : "r"(laddr), "r"(peer));
    return r;
}

// 128-MAC dot with NaN-retry over LOCAL h (intra-CTA visibility is fast, so
// retries are rare/short). Volatile 16B LDS; non-NaN sum proves all 128
// inputs are real data.
__device__ __forceinline__ float dot128_retry(const unsigned long long* __restrict__ wh,
                                              unsigned int a) {
    float part;
    unsigned int bad;
    do {
        unsigned long long c0 = 0ull, c1 = 0ull, c2 = 0ull, c3 = 0ull;
#pragma unroll
        for (int m = 0; m < 32; m += 2) {
            unsigned long long x0, x1, x2, x3;
            asm volatile("ld.volatile.shared.v2.u64 {%0, %1}, [%2];"
                         : "=l"(x0), "=l"(x1) : "r"(a + m * 16));
            asm volatile("ld.volatile.shared.v2.u64 {%0, %1}, [%2];"
                         : "=l"(x2), "=l"(x3) : "r"(a + m * 16 + 16));
            fma2(c0, wh[2 * m],     x0);
            fma2(c1, wh[2 * m + 1], x1);
            fma2(c2, wh[2 * m + 2], x2);
            fma2(c3, wh[2 * m + 3], x3);
        }
        float2 f0 = unpack2(c0), f1 = unpack2(c1);
        float2 f2 = unpack2(c2), f3 = unpack2(c3);
        part = ((f0.x + f0.y) + (f1.x + f1.y)) + ((f2.x + f2.y) + (f3.x + f3.y));
        unsigned int v = __float_as_uint(part);          // fast-math-immune
        bad = ((v & 0x7fffffffu) > 0x7f800000u) ? 1u : 0u;
    } while (__any_sync(0xffffffffu, bad));
    return part;
}

// ---------------------------------------------------------------------------
// Recurrence: K-SPLIT across a 2-CTA cluster + single-word NaN sentinels.
// Cluster c = batch b. CTA rank r owns k-half r of h (hbuf holds only the
// 128 locally-finalized outputs, which ARE k-half r of the next h).
//   warps 4..7 (producers): retry-dot over local hbuf with weights
//       Wh[j_peer][local k-half]; push the resulting SINGLE partial float
//       into the peer's pbuf slot (st.shared::cluster, weak).
//   warps 0..3 (finalizers): own local dot (same k-half, weights
//       Wh[j_local][local k-half]) runs DURING the peer partial's transit;
//       then spin on ONE pbuf word (arrival proof is complete: the word IS
//       the whole payload), add + xi + bias, tanh, store h + stream g_hs.
// No barrier / fence / flag in the loop. Wipe discipline (R10-proven):
// finalizer j wipes its read slots hbuf[(t+2)&3][j], pbuf[(t+2)&3][j]; the
// cross-CTA causality chain (our finalizer at t => our producers done t-1
// => all our finalizers done t-2) makes 4-deep rings race-free.
// ---------------------------------------------------------------------------
__global__ void __launch_bounds__(256, 1) __cluster_dims__(2, 1, 1)
elman_recurrence(const float* __restrict__ input,
                 const float* __restrict__ Wi,
                 const float* __restrict__ bi,
                 const float* __restrict__ Wh,
                 const float* __restrict__ bh) {
    __shared__ __align__(16) float hbuf[NBUF][HPAD];   // local k-half of h
    __shared__ __align__(16) float pbuf[NBUF][HPAD];   // incoming partials

    const int tid  = threadIdx.x;
    const int rank = blockIdx.x & 1;
    const int b    = blockIdx.x >> 1;
    const unsigned int peer = rank ^ 1;
    const bool is_fin = (tid < 128);         // warps 0-3 finalize local outputs
    const int  li = tid & 127;

    // output row whose local-k partial this thread computes
    const int j_out = (is_fin ? 128 * rank : 128 * (1 - rank)) + li;

    // --- loop-invariant weights Wh[j_out][128*rank .. +128) in registers ---
    unsigned long long wh[64];
    {
        const ulonglong2* wsrc =
            (const ulonglong2*)(Wh + (size_t)j_out * HID + rank * HALF);
#pragma unroll
        for (int m = 0; m < 32; ++m) {
            ulonglong2 v = __ldg(wsrc + m);
            wh[2 * m]     = v.x;
            wh[2 * m + 1] = v.y;
        }
    }

    // --- finalizer constants ---
    float4 wi4 = make_float4(0.f, 0.f, 0.f, 0.f);
    float  cb  = 0.f;
    if (is_fin) {
        wi4 = __ldg((const float4*)(Wi + (size_t)j_out * IN_DIM));
        cb  = __ldg(bi + j_out) + __ldg(bh + j_out);
    }

    // --- addresses ---
    unsigned int hb_rd[NBUF];    // dot read base: &hbuf[s][0]
    unsigned int h_sl[NBUF];     // finalizer: &hbuf[s][li] (write + wipe)
    unsigned int p_sl[NBUF];     // finalizer: &pbuf[s][li] (spin + wipe)
    unsigned int r_p[NBUF];      // producer: peer's &pbuf[s][li]
#pragma unroll
    for (int s = 0; s < NBUF; ++s) {
        hb_rd[s] = smem_u32(&hbuf[s][0]);
        h_sl[s]  = smem_u32(&hbuf[s][li]);
        p_sl[s]  = smem_u32(&pbuf[s][li]);
        r_p[s]   = mapa_peer(smem_u32(&pbuf[s][li]), peer);
    }

    // --- init: hbuf[0] = 0; hbuf[1..3] = NaN; pbuf[all] = NaN ---
    if (tid < HALF) {
        hbuf[0][tid] = 0.f;
#pragma unroll
        for (int s = 1; s < NBUF; ++s)
            ((unsigned int*)&hbuf[s][0])[tid] = 0x7fffffffu;
#pragma unroll
        for (int s = 0; s < NBUF; ++s)
            ((unsigned int*)&pbuf[s][0])[tid] = 0x7fffffffu;
    }
    __syncthreads();
    // one-time: peer must observe our init before its first pushes land here
    asm volatile("barrier.cluster.arrive.aligned;" ::: "memory");
    asm volatile("barrier.cluster.wait.aligned;" ::: "memory");

    float4 xin = make_float4(0.f, 0.f, 0.f, 0.f);
    if (is_fin)
        xin = __ldg((const float4*)(input + (size_t)b * IN_DIM));

    float* hsb = g_hs + (size_t)b * HID + (size_t)j_out;

    for (int t = 0; t < T_STEPS; ++t) {
        const int cur = t & 3;
        const int nxt = (t + 1) & 3;
        const int wb  = (t + 2) & 3;

        if (!is_fin) {
            // ---- producer: local dot, push ONE partial float to peer ----
            float part = dot128_retry(wh, hb_rd[cur]);
            asm volatile("st.shared::cluster.f32 [%0], %1;"
                         :: "r"(r_p[cur]), "f"(part) : "memory");
        } else {
            // ---- finalizer ----
            // wipe my read slots in the ring buffer due for reuse
            asm volatile("st.volatile.shared.u32 [%0], %1;"
                         :: "r"(h_sl[wb]), "r"(0x7fffffffu) : "memory");
            asm volatile("st.volatile.shared.u32 [%0], %1;"
                         :: "r"(p_sl[wb]), "r"(0x7fffffffu) : "memory");

            // prefetch next xi (independent)
            float4 xnext = xin;
            if (t + 1 < T_STEPS)
                xnext = __ldg((const float4*)(input +
                              ((size_t)(t + 1) * BATCH + b) * IN_DIM));

            // local-k dot runs while the peer's partial is in transit
            float pre = dot128_retry(wh, hb_rd[cur]) +
                        xin.x * wi4.x + xin.y * wi4.y +
                        xin.z * wi4.z + xin.w * wi4.w + cb;

            // spin on my single incoming word (= the complete payload)
            unsigned int pv;
            do {
                asm volatile("ld.volatile.shared.b32 %0, [%1];"
                             : "=r"(pv) : "r"(p_sl[cur]));
            } while ((pv & 0x7fffffffu) > 0x7f800000u);

            float hn = tanhf(pre + __uint_as_float(pv));
            asm volatile("st.volatile.shared.u32 [%0], %1;"     // h(t+1) local
                         :: "r"(h_sl[nxt]), "r"(__float_as_uint(hn)) : "memory");
            hsb[(size_t)t * (BATCH * HID)] = hn;                // stream g_hs
            xin = xnext;
        }
        // NO __syncthreads / fence / flag in the loop
    }

    // keep SMEM alive until the peer's last in-flight pushes are irrelevant
    asm volatile("barrier.cluster.arrive.aligned;" ::: "memory");
    asm volatile("barrier.cluster.wait.aligned;" ::: "memory");
}

// ---------------------------------------------------------------------------
// Output head: out[t,b,:] = tanh(hs[t,b,:] @ Wf^T + bf). One warp per row,
// grid-stride; memory-bound (streams 268 MB of hs at ~69% of HBM peak).
// ---------------------------------------------------------------------------
__global__ void __launch_bounds__(256)
elman_head(const float* __restrict__ Wf,
           const float* __restrict__ bf,
           float* __restrict__ out) {
    const int lane   = threadIdx.x & 31;
    const int gwarp  = (blockIdx.x * blockDim.x + threadIdx.x) >> 5;
    const int nwarps = (gridDim.x * blockDim.x) >> 5;

    const float bf0 = __ldg(bf + 0);
    const float bf1 = __ldg(bf + 1);

    const float4* wf0p = (const float4*)(Wf) + lane * 2;
    const float4* wf1p = (const float4*)(Wf + HID) + lane * 2;
    const float4 w00 = __ldg(wf0p), w01 = __ldg(wf0p + 1);
    const float4 w10 = __ldg(wf1p), w11 = __ldg(wf1p + 1);

    const int nrows = T_STEPS * BATCH;
    for (int row = gwarp; row < nrows; row += nwarps) {
        const float4* h = (const float4*)(g_hs + (size_t)row * HID) + lane * 2;
        float4 h0 = h[0], h1 = h[1];
        float s0 = h0.x * w00.x + h0.y * w00.y + h0.z * w00.z + h0.w * w00.w +
                   h1.x * w01.x + h1.y * w01.y + h1.z * w01.z + h1.w * w01.w;
        float s1 = h0.x * w10.x + h0.y * w10.y + h0.z * w10.z + h0.w * w10.w +
                   h1.x * w11.x + h1.y * w11.y + h1.z * w11.z + h1.w * w11.w;
#pragma unroll
        for (int o = 16; o; o >>= 1) {
            s0 += __shfl_xor_sync(0xffffffffu, s0, o);
            s1 += __shfl_xor_sync(0xffffffffu, s1, o);
        }
        if (lane == 0) {
            out[(size_t)row * OUT_DIM + 0] = tanhf(s0 + bf0);
            out[(size_t)row * OUT_DIM + 1] = tanhf(s1 + bf1);
        }
    }
}

// nop as the 3rd launch: the harness prepends 2 launches, so ncu's capture
// (skip 5, take #6) lands on OUR 4th launch = the 2nd call's RECURRENCE.
__global__ void elman_nop() {}

extern "C" void kernel_launch(void* const* d_in, const int* in_sizes, int n_in,
                              void* d_out, int out_size) {
    // metadata order: input, target, Wi, bi, Wh, bh, Wf, bf
    const float* input = (const float*)d_in[0];
    const float* Wi = (const float*)d_in[2];
    const float* bi = (const float*)d_in[3];
    const float* Wh = (const float*)d_in[4];
    const float* bh = (const float*)d_in[5];
    const float* Wf = (const float*)d_in[6];
    const float* bf = (const float*)d_in[7];
    float* out = (float*)d_out;

    // 64 clusters x 2 CTAs, 1 batch per cluster
    elman_recurrence<<<2 * BATCH, 256>>>(input, Wi, bi, Wh, bh);
    elman_head<<<2048, 256>>>(Wf, bf, out);
    elman_nop<<<1, 32>>>();
}